// round 3
// baseline (speedup 1.0000x reference)
#include <cuda_runtime.h>
#include <cstdint>

// 2x2 Haar DWT, fp32.
// Input:  x  (16, 1, 2048, 2048)  -> 64M floats
// Output: [ll | lh | hl | hh], each (16, 1, 1024, 1024), concatenated -> 64M floats
//
// ll = 0.5*( a + b + c + d)
// lh = 0.5*(-a + b - c + d)
// hl = 0.5*(-a - b + c + d)
// hh = 0.5*( a - b - c + d)
// with a=x[2i,2j], b=x[2i,2j+1], c=x[2i+1,2j], d=x[2i+1,2j+1]
// _safe(): non-finite -> 0 on inputs and outputs.

static constexpr int B   = 16;
static constexpr int H   = 2048;
static constexpr int W   = 2048;
static constexpr int OH  = H / 2;   // 1024
static constexpr int OW  = W / 2;   // 1024
static constexpr long long SUB_ELEMS = (long long)B * OH * OW;  // 16M per subband

__device__ __forceinline__ float safef(float v) {
    // finite check via exponent bits (robust under fast-math)
    return ((__float_as_uint(v) & 0x7f800000u) == 0x7f800000u) ? 0.0f : v;
}

__device__ __forceinline__ float4 safe4(float4 v) {
    v.x = safef(v.x); v.y = safef(v.y); v.z = safef(v.z); v.w = safef(v.w);
    return v;
}

__global__ __launch_bounds__(256)
void dwt2d_haar_kernel(const float* __restrict__ x, float* __restrict__ out) {
    // Each thread: 4 output columns of one output row.
    // Total threads = B * OH * (OW/4) = 16 * 1024 * 256 = 4,194,304
    const int t = blockIdx.x * blockDim.x + threadIdx.x;
    const int groups_per_row = OW / 4;                    // 256
    const int g = t & (groups_per_row - 1);               // col group
    const int rn = t >> 8;                                // r + n*OH combined
    const int r = rn & (OH - 1);
    const int n = rn >> 10;
    if (n >= B) return;

    const long long in_base  = (long long)n * H * W + (long long)(2 * r) * W + 8 * g;
    const float4* row0 = (const float4*)(x + in_base);
    const float4* row1 = (const float4*)(x + in_base + W);

    float4 p0 = safe4(row0[0]);   // a0 b0 a1 b1
    float4 p1 = safe4(row0[1]);   // a2 b2 a3 b3
    float4 q0 = safe4(row1[0]);   // c0 d0 c1 d1
    float4 q1 = safe4(row1[1]);   // c2 d2 c3 d3

    float a[4] = {p0.x, p0.z, p1.x, p1.z};
    float b[4] = {p0.y, p0.w, p1.y, p1.w};
    float c[4] = {q0.x, q0.z, q1.x, q1.z};
    float d[4] = {q0.y, q0.w, q1.y, q1.w};

    float4 ll, lh, hl, hh;
    float* llp = &ll.x; float* lhp = &lh.x; float* hlp = &hl.x; float* hhp = &hh.x;
#pragma unroll
    for (int i = 0; i < 4; i++) {
        float s_ab = a[i] + b[i];
        float d_ab = b[i] - a[i];
        float s_cd = c[i] + d[i];
        float d_cd = d[i] - c[i];
        llp[i] = safef(0.5f * (s_ab + s_cd));
        lhp[i] = safef(0.5f * (d_ab + d_cd));
        hlp[i] = safef(0.5f * (s_cd - s_ab));
        hhp[i] = safef(0.5f * (d_cd - d_ab));
    }

    const long long out_base = (long long)n * OH * OW + (long long)r * OW + 4 * g;
    float4* o_ll = (float4*)(out + out_base);
    float4* o_lh = (float4*)(out + out_base + SUB_ELEMS);
    float4* o_hl = (float4*)(out + out_base + 2 * SUB_ELEMS);
    float4* o_hh = (float4*)(out + out_base + 3 * SUB_ELEMS);
    o_ll[0] = ll;
    o_lh[0] = lh;
    o_hl[0] = hl;
    o_hh[0] = hh;
}

extern "C" void kernel_launch(void* const* d_in, const int* in_sizes, int n_in,
                              void* d_out, int out_size) {
    const float* x = (const float*)d_in[0];
    float* out = (float*)d_out;
    const long long total_threads = (long long)B * OH * (OW / 4);  // 4,194,304
    const int block = 256;
    const int grid = (int)((total_threads + block - 1) / block);   // 16384
    dwt2d_haar_kernel<<<grid, block>>>(x, out);
}